// round 6
// baseline (speedup 1.0000x reference)
#include <cuda_runtime.h>
#include <cuda_fp16.h>
#include <cstdint>
#include <cstddef>

// ---------------- problem constants ----------------
namespace {
constexpr int kT = 8192, kD = 2048, kF = 4096, kE = 8;
constexpr int TMm = 128;                 // CTA tile M
constexpr int TN  = 256;                 // CTA tile N
constexpr int ROWT = kT / TMm + kE;      // 72 padded row tiles max
constexpr int TPAD = ROWT * TMm;         // 9216
constexpr int BK = 64;                   // halves per K chunk (128 B rows)
constexpr int ST = 4;                    // pipeline stages
constexpr int A_BYTES = TMm * BK * 2;    // 16 KB
constexpr int B_BYTES = TN * BK * 2;     // 32 KB
constexpr int STG = A_BYTES + B_BYTES;   // 48 KB
constexpr int SMEM_BYTES = ST * STG;     // 192 KB
constexpr int NTH = 256;                 // 8 warps

constexpr long long W1_N8 = ((long long)kE * kF * kD) / 8;   // 8388608
constexpr long long W2_N8 = ((long long)kE * kD * kF) / 8;   // 8388608
// fused-kernel tile schedule
constexpr int CVT2 = 256;                          // w2-cvt slices
constexpr int CVT_CHUNK = (int)(W2_N8 / CVT2);     // 32768 uint4 per slice
constexpr int NT1 = (kF / TN) * ROWT;              // 1152 GEMM1 tiles
constexpr int NT2 = (kD / TN) * ROWT;              // 576  GEMM2 tiles
constexpr int MIX = 3 * CVT2;                      // 768 interleaved ids
constexpr int PH1 = NT1 + CVT2;                    // 1408
constexpr int TOTAL = PH1 + NT2;                   // 1984
constexpr int NCTA = 152;                          // persistent CTAs
}

// ---------------- scratch globals ----------------
__device__ int g_counts[kE];
__device__ int g_cursor[kE];
__device__ int g_rowtoken[TPAD];
__device__ int g_tile_expert[ROWT];
__device__ int g_ctr;                    // persistent tile counter
__device__ int g_cvtdone;                // completed w2-cvt slices
__device__ int g_done1[ROWT];            // per-rt completed GEMM1 x-tiles
__device__ __half g_xperm[(size_t)TPAD * kD];
__device__ __half g_w1h[(size_t)kE * kF * kD];
__device__ __half g_w2h[(size_t)kE * kD * kF];
__device__ __half g_h1h[(size_t)TPAD * kF];

// ---------------- helpers ----------------
__device__ __forceinline__ uint32_t smem_u32(const void* p) {
    uint32_t a;
    asm("{ .reg .u64 t; cvta.to.shared.u64 t, %1; cvt.u32.u64 %0, t; }" : "=r"(a) : "l"(p));
    return a;
}
__device__ __forceinline__ void ldsm_x4(uint32_t* r, uint32_t addr) {
    asm volatile("ldmatrix.sync.aligned.m8n8.x4.shared.b16 {%0,%1,%2,%3}, [%4];"
                 : "=r"(r[0]), "=r"(r[1]), "=r"(r[2]), "=r"(r[3]) : "r"(addr));
}
__device__ __forceinline__ void mma_f16(float* c, const uint32_t* a, uint32_t b0, uint32_t b1) {
    asm volatile(
        "mma.sync.aligned.m16n8k16.row.col.f32.f16.f16.f32 "
        "{%0,%1,%2,%3}, {%4,%5,%6,%7}, {%8,%9}, {%0,%1,%2,%3};\n"
        : "+f"(c[0]), "+f"(c[1]), "+f"(c[2]), "+f"(c[3])
        : "r"(a[0]), "r"(a[1]), "r"(a[2]), "r"(a[3]), "r"(b0), "r"(b1));
}
__device__ __forceinline__ void cp_async16(uint32_t dst, const void* src) {
    asm volatile("cp.async.cg.shared.global [%0], [%1], 16;" :: "r"(dst), "l"(src));
}
__device__ __forceinline__ void cvt8(const float4* __restrict__ s, uint4* __restrict__ d) {
    float4 a = s[0], b = s[1];
    __half2 h0 = __floats2half2_rn(a.x, a.y), h1 = __floats2half2_rn(a.z, a.w);
    __half2 h2 = __floats2half2_rn(b.x, b.y), h3 = __floats2half2_rn(b.z, b.w);
    uint4 o;
    o.x = *(uint32_t*)&h0; o.y = *(uint32_t*)&h1;
    o.z = *(uint32_t*)&h2; o.w = *(uint32_t*)&h3;
    *d = o;
}
__device__ __forceinline__ int ld_acquire(const int* p) {
    int v;
    asm volatile("ld.acquire.gpu.global.b32 %0, [%1];" : "=r"(v) : "l"(p) : "memory");
    return v;
}

// ---------------- routing ----------------
__global__ void k_route(const float* __restrict__ logits) {
    int t = blockIdx.x * blockDim.x + threadIdx.x;
    if (t < kE) g_counts[t] = 0;           // zeroed before any atomics below (same block 0 executes both? no!)
    __syncthreads();                        // only valid within block; counts zeroed by block 0 threads 0..7
    // NOTE: zero-init must be globally ordered before atomics -> do counts in k_zero below instead.
    if (t >= kT) return;
    const float* l = logits + (size_t)t * kE;
    int best = 0; float bv = l[0];
#pragma unroll
    for (int e = 1; e < kE; e++) { float v = l[e]; if (v > bv) { bv = v; best = e; } }
    ((int*)g_xperm)[t] = best;              // temp storage, overwritten by k_prep
}
// zero counters, then accumulate counts (separate kernel to order zeroing before atomics)
__global__ void k_count() {
    int t = blockIdx.x * blockDim.x + threadIdx.x;
    if (t >= kT) return;
    atomicAdd(&g_counts[((int*)g_xperm)[t]], 1);
}
__global__ void k_offsets() {        // single block, 256 threads
    if (threadIdx.x == 0) {
        int off = 0;
        for (int e = 0; e < kE; e++) {
            g_cursor[e] = off;
            int nt = (g_counts[e] + TMm - 1) / TMm;
            for (int i = 0; i < nt; i++) g_tile_expert[off / TMm + i] = e;
            off += nt * TMm;
        }
        for (int rt = off / TMm; rt < ROWT; rt++) g_tile_expert[rt] = -1;
        g_ctr = 0;
        g_cvtdone = 0;
    }
    for (int i = threadIdx.x; i < TPAD; i += blockDim.x) g_rowtoken[i] = -1;
    for (int i = threadIdx.x; i < ROWT; i += blockDim.x) g_done1[i] = 0;
}
__global__ void k_scatter() {
    int t = blockIdx.x * blockDim.x + threadIdx.x;
    if (t >= kT) return;
    int e = ((int*)g_xperm)[t];
    int pos = atomicAdd(&g_cursor[e], 1);
    g_rowtoken[pos] = t;
}
// w1 fp32->fp16 + token gather/convert/zero-pad, one DRAM-bound pass
__global__ void k_prep(const float4* __restrict__ w1, const float4* __restrict__ hs) {
    long long i = (long long)blockIdx.x * blockDim.x + threadIdx.x;
    if (i < W1_N8) cvt8(w1 + 2 * (size_t)i, ((uint4*)g_w1h) + i);
    if (i < (long long)TPAD * 256) {
        int row = (int)(i >> 8);
        int q = (int)(i & 255);
        int tok = g_rowtoken[row];
        uint4 o = make_uint4(0, 0, 0, 0);
        if (tok >= 0) {
            const float4* s = hs + (size_t)tok * (kD / 4) + 2 * q;
            float4 a = s[0], b = s[1];
            __half2 h0 = __floats2half2_rn(a.x, a.y), h1 = __floats2half2_rn(a.z, a.w);
            __half2 h2 = __floats2half2_rn(b.x, b.y), h3 = __floats2half2_rn(b.z, b.w);
            o.x = *(uint32_t*)&h0; o.y = *(uint32_t*)&h1;
            o.z = *(uint32_t*)&h2; o.w = *(uint32_t*)&h3;
        }
        ((uint4*)g_xperm)[i] = o;
    }
}

// ---------------- GEMM tile body (device) ----------------
// CTA tile 128x256, 8 warps (2 M x 4 N), warp tile 64x64, ldmatrix + 4-stage cp.async.
template <bool FIRST>
__device__ __forceinline__ void gemm_tile(int rt, int xblk, uint32_t sb, float* __restrict__ out)
{
    constexpr int N = FIRST ? kF : kD;
    constexpr int K = FIRST ? kD : kF;
    constexpr int NC = K / BK;
    const int e = g_tile_expert[rt];
    if (e < 0) return;
    const int rowbase = rt * TMm;
    const int colbase = xblk * TN;

    const int tid = threadIdx.x;
    const int warp = tid >> 5, lane = tid & 31;
    const int wm = warp & 1, wn = warp >> 1;

    const __half* Abase = FIRST ? g_xperm : g_h1h;
    const __half* Wb = (FIRST ? g_w1h : g_w2h) + (size_t)e * ((size_t)N * K);

    const int q = tid & 7, r = tid >> 3;                 // r: 0..31
    const __half* aptr = Abase + (size_t)(rowbase + r) * K + q * 8;
    const __half* bptr = Wb + (size_t)(colbase + r) * K + q * 8;
    const uint32_t dA = (uint32_t)(r * 128 + ((q ^ (r & 7)) << 4));

    auto prefetch = [&](int c) {
        const uint32_t base = sb + (uint32_t)((c & (ST - 1)) * STG);
        const __half* ap = aptr + c * BK;
#pragma unroll
        for (int p = 0; p < 4; p++)
            cp_async16(base + dA + (uint32_t)(p * 32 * 128), ap + (size_t)p * 32 * K);
        const __half* bp = bptr + c * BK;
#pragma unroll
        for (int p = 0; p < 8; p++)
            cp_async16(base + A_BYTES + dA + (uint32_t)(p * 32 * 128), bp + (size_t)p * 32 * K);
        asm volatile("cp.async.commit_group;" ::: "memory");
    };

    prefetch(0);
    prefetch(1);
    prefetch(2);

    const int rowA = wm * 64 + (lane & 15);
    const int kgA = lane >> 4;
    const int rowB = wn * 64 + ((lane >> 4) << 3) + (lane & 7);
    const int kgB = (lane >> 3) & 1;

    float acc[4][8][4];
#pragma unroll
    for (int i = 0; i < 4; i++)
#pragma unroll
        for (int j = 0; j < 8; j++)
#pragma unroll
            for (int v = 0; v < 4; v++) acc[i][j][v] = 0.f;

    for (int c = 0; c < NC; c++) {
        // tail-correct wait: guarantee group c complete before reading its stage
        if (c < NC - 2)      asm volatile("cp.async.wait_group 2;" ::: "memory");
        else if (c == NC - 2) asm volatile("cp.async.wait_group 1;" ::: "memory");
        else                 asm volatile("cp.async.wait_group 0;" ::: "memory");
        __syncthreads();
        if (c + 3 < NC) prefetch(c + 3);

        const uint32_t stA = sb + (uint32_t)((c & (ST - 1)) * STG);
        const uint32_t stB = stA + A_BYTES;
#pragma unroll
        for (int s = 0; s < 4; s++) {
            uint32_t a[4][4];
#pragma unroll
            for (int mi = 0; mi < 4; mi++) {
                const int rr = rowA + mi * 16;
                ldsm_x4(a[mi], stA + (uint32_t)(rr * 128 + (((2 * s + kgA) ^ (rr & 7)) << 4)));
            }
            uint32_t b[4][4];
#pragma unroll
            for (int nj2 = 0; nj2 < 4; nj2++) {
                const int rr = rowB + nj2 * 16;
                ldsm_x4(b[nj2], stB + (uint32_t)(rr * 128 + (((2 * s + kgB) ^ (rr & 7)) << 4)));
            }
#pragma unroll
            for (int mi = 0; mi < 4; mi++)
#pragma unroll
                for (int nj = 0; nj < 8; nj++)
                    mma_f16(acc[mi][nj], a[mi], b[nj >> 1][(nj & 1) * 2], b[nj >> 1][(nj & 1) * 2 + 1]);
        }
    }

    // ---- epilogue ----
    const int g = lane >> 2, tig = lane & 3;
#pragma unroll
    for (int mi = 0; mi < 4; mi++) {
#pragma unroll
        for (int rr = 0; rr < 2; rr++) {
            const int lrow = rowbase + wm * 64 + mi * 16 + g + rr * 8;
            if (FIRST) {
                __half* hp = g_h1h + (size_t)lrow * kF + colbase;
#pragma unroll
                for (int nj = 0; nj < 8; nj++) {
                    const int col = wn * 64 + nj * 8 + tig * 2;
                    float v0 = acc[mi][nj][rr * 2 + 0];
                    float v1 = acc[mi][nj][rr * 2 + 1];
                    v0 = v0 / (1.f + __expf(-v0));       // SiLU
                    v1 = v1 / (1.f + __expf(-v1));
                    __half2 h = __floats2half2_rn(v0, v1);
                    *(uint32_t*)(hp + col) = *(uint32_t*)&h;
                }
            } else {
                const int tok = g_rowtoken[lrow];
                if (tok >= 0) {
                    float* op = out + (size_t)tok * kD + colbase;
#pragma unroll
                    for (int nj = 0; nj < 8; nj++) {
                        const int col = wn * 64 + nj * 8 + tig * 2;
                        float2 st;
                        st.x = acc[mi][nj][rr * 2 + 0];
                        st.y = acc[mi][nj][rr * 2 + 1];
                        *(float2*)(op + col) = st;
                    }
                }
            }
        }
    }
}

// ---------------- fused persistent kernel ----------------
// tile ids: [0,768): id%3==2 -> w2-cvt slice id/3, else GEMM1 tile id-(id+1)/3
//           [768,1408): GEMM1 tile id-256
//           [1408,1984): GEMM2 tile id-1408 (waits on cvt + per-rt GEMM1 done)
__global__ __launch_bounds__(NTH, 1) void k_fused(const float4* __restrict__ w2src,
                                                  float* __restrict__ out)
{
    extern __shared__ char smem[];
    __shared__ int s_id;
    const uint32_t sb = smem_u32(smem);
    const int tid = threadIdx.x;

    for (;;) {
        __syncthreads();                       // protect s_id reuse
        if (tid == 0) s_id = atomicAdd(&g_ctr, 1);
        __syncthreads();
        const int id = s_id;
        if (id >= TOTAL) return;

        if (id < MIX && (id % 3) == 2) {
            // ---- w2 fp32->fp16 slice ----
            const int slice = id / 3;
            long long base = (long long)slice * CVT_CHUNK;
            uint4* dst = (uint4*)g_w2h;
#pragma unroll 4
            for (int i = tid; i < CVT_CHUNK; i += NTH)
                cvt8(w2src + 2 * (size_t)(base + i), dst + base + i);
            __threadfence();
            __syncthreads();
            if (tid == 0) atomicAdd(&g_cvtdone, 1);
        } else if (id < PH1) {
            // ---- GEMM1 tile ----
            const int g1 = (id < MIX) ? (id - (id + 1) / 3) : (id - CVT2);
            const int rt = g1 >> 4, xblk = g1 & 15;
            gemm_tile<true>(rt, xblk, sb, out);
            __threadfence();
            __syncthreads();
            if (tid == 0) atomicAdd(&g_done1[rt], 1);
        } else {
            // ---- GEMM2 tile ----
            const int g2 = id - PH1;
            const int rt = g2 >> 3, xblk = g2 & 7;
            if (g_tile_expert[rt] < 0) continue;
            if (tid == 0) {
                while (ld_acquire(&g_cvtdone) < CVT2) __nanosleep(256);
                while (ld_acquire(&g_done1[rt]) < 16) __nanosleep(256);
            }
            __syncthreads();
            gemm_tile<false>(rt, xblk, sb, out);
        }
    }
}

// ---------------- entry ----------------
extern "C" void kernel_launch(void* const* d_in, const int* in_sizes, int n_in,
                              void* d_out, int out_size) {
    const float* hs     = (const float*)d_in[0];
    const float* logits = (const float*)d_in[1];
    const float* w1     = (const float*)d_in[2];
    const float* w2     = (const float*)d_in[3];
    float* out = (float*)d_out;

    cudaFuncSetAttribute(k_fused, cudaFuncAttributeMaxDynamicSharedMemorySize, SMEM_BYTES);

    k_route<<<kT / 256, 256>>>(logits);            // also stashes assignments
    // zero counts first via k_offsets? counts accumulated in k_count after explicit zero:
    // (g_counts zeroing happens in k_route block 0? -> do it robustly here)
    k_count<<<kT / 256, 256>>>();
    k_offsets<<<1, 256>>>();
    k_scatter<<<kT / 256, 256>>>();
    k_prep<<<(unsigned)((W1_N8 + 255) / 256), 256>>>((const float4*)w1, (const float4*)hs);

    k_fused<<<NCTA, NTH, SMEM_BYTES>>>((const float4*)w2, out);
}

// round 7
// speedup vs baseline: 1.1736x; 1.1736x over previous
#include <cuda_runtime.h>
#include <cuda_fp16.h>
#include <cstdint>
#include <cstddef>

// ---------------- problem constants ----------------
namespace {
constexpr int kT = 8192, kD = 2048, kF = 4096, kE = 8;
constexpr int TMm = 128;                 // CTA tile M
constexpr int TN  = 256;                 // CTA tile N
constexpr int ROWT = kT / TMm + kE;      // 72 padded row tiles max
constexpr int TPAD = ROWT * TMm;         // 9216
constexpr int BK = 64;                   // halves per K chunk (128 B rows)
constexpr int ST = 4;                    // pipeline stages
constexpr int A_BYTES = TMm * BK * 2;    // 16 KB
constexpr int B_BYTES = TN * BK * 2;     // 32 KB
constexpr int STG = A_BYTES + B_BYTES;   // 48 KB
constexpr int SMEM_BYTES = ST * STG;     // 192 KB
constexpr int NTH = 256;                 // 8 warps
// w2 conversion folded into GEMM1 grid
constexpr int CVTY = 32;                 // 32 interleaved y-slices (x16 CTAs)
constexpr int CVT_THREADS = CVTY * 16 * NTH;         // 131072
constexpr long long W2_N8 = ((long long)kE * kD * kF) / 8;   // 8388608 uint4
}

// ---------------- scratch globals ----------------
__device__ int g_counts[kE];
__device__ int g_cursor[kE];
__device__ int g_rowtoken[TPAD];
__device__ int g_tile_expert[ROWT];
__device__ __half g_xperm[(size_t)TPAD * kD];     // permuted+padded fp16 tokens
__device__ __half g_w1h[(size_t)kE * kF * kD];
__device__ __half g_w2h[(size_t)kE * kD * kF];
__device__ __half g_h1h[(size_t)TPAD * kF];       // silu(x@w1^T) fp16

// ---------------- helpers ----------------
__device__ __forceinline__ uint32_t smem_u32(const void* p) {
    uint32_t a;
    asm("{ .reg .u64 t; cvta.to.shared.u64 t, %1; cvt.u32.u64 %0, t; }" : "=r"(a) : "l"(p));
    return a;
}
__device__ __forceinline__ void ldsm_x4(uint32_t* r, uint32_t addr) {
    asm volatile("ldmatrix.sync.aligned.m8n8.x4.shared.b16 {%0,%1,%2,%3}, [%4];"
                 : "=r"(r[0]), "=r"(r[1]), "=r"(r[2]), "=r"(r[3]) : "r"(addr));
}
__device__ __forceinline__ void mma_f16(float* c, const uint32_t* a, uint32_t b0, uint32_t b1) {
    asm volatile(
        "mma.sync.aligned.m16n8k16.row.col.f32.f16.f16.f32 "
        "{%0,%1,%2,%3}, {%4,%5,%6,%7}, {%8,%9}, {%0,%1,%2,%3};\n"
        : "+f"(c[0]), "+f"(c[1]), "+f"(c[2]), "+f"(c[3])
        : "r"(a[0]), "r"(a[1]), "r"(a[2]), "r"(a[3]), "r"(b0), "r"(b1));
}
__device__ __forceinline__ void cp_async16(uint32_t dst, const void* src) {
    asm volatile("cp.async.cg.shared.global [%0], [%1], 16;" :: "r"(dst), "l"(src));
}
__device__ __forceinline__ void cvt8(const float4* __restrict__ s, uint4* __restrict__ d) {
    float4 a = s[0], b = s[1];
    __half2 h0 = __floats2half2_rn(a.x, a.y), h1 = __floats2half2_rn(a.z, a.w);
    __half2 h2 = __floats2half2_rn(b.x, b.y), h3 = __floats2half2_rn(b.z, b.w);
    uint4 o;
    o.x = *(uint32_t*)&h0; o.y = *(uint32_t*)&h1;
    o.z = *(uint32_t*)&h2; o.w = *(uint32_t*)&h3;
    *d = o;
}

// ---------------- w1 convert (+ zero routing counters) ----------------
__global__ void k_cvt_w1(const float4* __restrict__ src, uint4* __restrict__ dst, int n8) {
    int i = blockIdx.x * blockDim.x + threadIdx.x;
    if (i < kE) g_counts[i] = 0;
    if (i >= n8) return;
    cvt8(src + 2 * (size_t)i, dst + i);
}

// ---------------- routing ----------------
__global__ void k_route(const float* __restrict__ logits) {
    int t = blockIdx.x * blockDim.x + threadIdx.x;
    if (t >= kT) return;
    const float* l = logits + (size_t)t * kE;
    int best = 0; float bv = l[0];
#pragma unroll
    for (int e = 1; e < kE; e++) { float v = l[e]; if (v > bv) { bv = v; best = e; } }
    atomicAdd(&g_counts[best], 1);
    ((int*)g_xperm)[t] = best;     // temp storage, overwritten by k_permute later
}
__global__ void k_offsets() {        // single block, 256 threads
    if (threadIdx.x == 0) {
        int off = 0;
        for (int e = 0; e < kE; e++) {
            g_cursor[e] = off;
            int nt = (g_counts[e] + TMm - 1) / TMm;
            for (int i = 0; i < nt; i++) g_tile_expert[off / TMm + i] = e;
            off += nt * TMm;
        }
        for (int rt = off / TMm; rt < ROWT; rt++) g_tile_expert[rt] = -1;
    }
    for (int i = threadIdx.x; i < TPAD; i += blockDim.x) g_rowtoken[i] = -1;
}
__global__ void k_scatter() {
    int t = blockIdx.x * blockDim.x + threadIdx.x;
    if (t >= kT) return;
    int e = ((int*)g_xperm)[t];
    int pos = atomicAdd(&g_cursor[e], 1);
    g_rowtoken[pos] = t;
}
// gather + fp32->fp16 convert + zero-pad into [TPAD, kD]
__global__ void k_permute(const float4* __restrict__ hs) {
    int i = blockIdx.x * blockDim.x + threadIdx.x;   // one per 8 halves
    int row = i >> 8;                                // kD/8 = 256 groups/row
    int q = i & 255;
    if (row >= TPAD) return;
    int tok = g_rowtoken[row];
    uint4 o = make_uint4(0, 0, 0, 0);
    if (tok >= 0) {
        const float4* s = hs + (size_t)tok * (kD / 4) + 2 * q;
        float4 a = s[0], b = s[1];
        __half2 h0 = __floats2half2_rn(a.x, a.y), h1 = __floats2half2_rn(a.z, a.w);
        __half2 h2 = __floats2half2_rn(b.x, b.y), h3 = __floats2half2_rn(b.z, b.w);
        o.x = *(uint32_t*)&h0; o.y = *(uint32_t*)&h1;
        o.z = *(uint32_t*)&h2; o.w = *(uint32_t*)&h3;
    }
    ((uint4*)g_xperm)[(size_t)row * 256 + q] = o;
}

// ---------------- fp16 HMMA GEMM -----------------------------------------
// CTA tile 128x256, 8 warps (2 M x 4 N), warp tile 64x64.
// 4-stage cp.async pipeline, 1 barrier/chunk, register-double-buffered LDSM.
// FIRST:  h1[TPAD,kF] = silu(g_xperm @ w1[e]^T); w2 fp16 conversion CTAs folded in.
// !FIRST: out[tok,kD] = g_h1h @ w2[e]^T   (scatter; pad rows dropped)
template <bool FIRST>
__global__ __launch_bounds__(NTH, 1) void k_gemm(const float4* __restrict__ w2src,
                                                 float* __restrict__ out)
{
    constexpr int N = FIRST ? kF : kD;
    constexpr int K = FIRST ? kD : kF;
    constexpr int NC = K / BK;

    int rt;
    if (FIRST) {
        // interleaved role mapping: y == 2 (mod 3) for y<96 -> w2 cvt slice
        const int y = blockIdx.y;
        if (y < 3 * CVTY && (y % 3) == 2) {
            const int slice = y / 3;
            long long base = ((long long)(slice * 16 + blockIdx.x) * NTH + threadIdx.x);
            uint4* dst = (uint4*)g_w2h;
#pragma unroll 4
            for (long long i = base; i < W2_N8; i += CVT_THREADS)
                cvt8(w2src + 2 * (size_t)i, dst + i);
            return;
        }
        rt = (y < 3 * CVTY) ? (y - (y + 1) / 3) : (y - CVTY);
    } else {
        rt = blockIdx.y;
    }

    const int e = g_tile_expert[rt];
    if (e < 0) return;
    const int rowbase = rt * TMm;
    const int colbase = blockIdx.x * TN;

    extern __shared__ char smem[];
    const uint32_t sb = smem_u32(smem);
    const int tid = threadIdx.x;
    const int warp = tid >> 5, lane = tid & 31;
    const int wm = warp & 1, wn = warp >> 1;

    const __half* Abase = FIRST ? g_xperm : g_h1h;
    const __half* Wb = (FIRST ? g_w1h : g_w2h) + (size_t)e * ((size_t)N * K);

    // ---- cp.async mapping: q = 16B group along K, r = base row ----
    const int q = tid & 7, r = tid >> 3;                 // r: 0..31
    const __half* aptr = Abase + (size_t)(rowbase + r) * K + q * 8;
    const __half* bptr = Wb + (size_t)(colbase + r) * K + q * 8;
    const uint32_t dA = (uint32_t)(r * 128 + ((q ^ (r & 7)) << 4));  // p*32 preserves row&7

    auto prefetch = [&](int c) {
        const uint32_t base = sb + (uint32_t)((c & (ST - 1)) * STG);
        const __half* ap = aptr + c * BK;
#pragma unroll
        for (int p = 0; p < 4; p++)
            cp_async16(base + dA + (uint32_t)(p * 32 * 128), ap + (size_t)p * 32 * K);
        const __half* bp = bptr + c * BK;
#pragma unroll
        for (int p = 0; p < 8; p++)
            cp_async16(base + A_BYTES + dA + (uint32_t)(p * 32 * 128), bp + (size_t)p * 32 * K);
        asm volatile("cp.async.commit_group;" ::: "memory");
    };

    prefetch(0);
    prefetch(1);
    prefetch(2);

    // ---- ldmatrix lane geometry ----
    const int rowA = wm * 64 + (lane & 15);
    const int kgA = lane >> 4;
    const int rowB = wn * 64 + ((lane >> 4) << 3) + (lane & 7);
    const int kgB = (lane >> 3) & 1;

    float acc[4][8][4];
#pragma unroll
    for (int i = 0; i < 4; i++)
#pragma unroll
        for (int j = 0; j < 8; j++)
#pragma unroll
            for (int v = 0; v < 4; v++) acc[i][j][v] = 0.f;

    // register double buffers for fragments
    uint32_t afr[2][4][4], bfr[2][4][4];

    auto load_frags = [&](uint32_t stA, uint32_t stB, int s, int buf) {
#pragma unroll
        for (int mi = 0; mi < 4; mi++) {
            const int rr = rowA + mi * 16;
            ldsm_x4(afr[buf][mi], stA + (uint32_t)(rr * 128 + (((2 * s + kgA) ^ (rr & 7)) << 4)));
        }
#pragma unroll
        for (int nj2 = 0; nj2 < 4; nj2++) {
            const int rr = rowB + nj2 * 16;
            ldsm_x4(bfr[buf][nj2], stB + (uint32_t)(rr * 128 + (((2 * s + kgB) ^ (rr & 7)) << 4)));
        }
    };

    for (int c = 0; c < NC; c++) {
        // tail-correct waits: group c must be complete before reading its stage
        if (c < NC - 2)       asm volatile("cp.async.wait_group 2;" ::: "memory");
        else if (c == NC - 2) asm volatile("cp.async.wait_group 1;" ::: "memory");
        else                  asm volatile("cp.async.wait_group 0;" ::: "memory");
        __syncthreads();                        // single barrier per chunk

        const uint32_t stA = sb + (uint32_t)((c & (ST - 1)) * STG);
        const uint32_t stB = stA + A_BYTES;

        load_frags(stA, stB, 0, 0);             // get LDSM going first
        if (c + 3 < NC) prefetch(c + 3);        // then issue next chunk's cp.async

#pragma unroll
        for (int s = 0; s < 4; s++) {           // 4 k16-steps, frag double-buffered
            if (s < 3) load_frags(stA, stB, s + 1, (s + 1) & 1);
            const int bsel = s & 1;
#pragma unroll
            for (int mi = 0; mi < 4; mi++)
#pragma unroll
                for (int nj = 0; nj < 8; nj++)
                    mma_f16(acc[mi][nj], afr[bsel][mi],
                            bfr[bsel][nj >> 1][(nj & 1) * 2],
                            bfr[bsel][nj >> 1][(nj & 1) * 2 + 1]);
        }
    }

    // ---- epilogue ----
    const int g = lane >> 2, tig = lane & 3;
#pragma unroll
    for (int mi = 0; mi < 4; mi++) {
#pragma unroll
        for (int rr = 0; rr < 2; rr++) {
            const int lrow = rowbase + wm * 64 + mi * 16 + g + rr * 8;
            if (FIRST) {
                __half* hp = g_h1h + (size_t)lrow * kF + colbase;
#pragma unroll
                for (int nj = 0; nj < 8; nj++) {
                    const int col = wn * 64 + nj * 8 + tig * 2;
                    float v0 = acc[mi][nj][rr * 2 + 0];
                    float v1 = acc[mi][nj][rr * 2 + 1];
                    v0 = v0 / (1.f + __expf(-v0));       // SiLU
                    v1 = v1 / (1.f + __expf(-v1));
                    __half2 h = __floats2half2_rn(v0, v1);
                    *(uint32_t*)(hp + col) = *(uint32_t*)&h;
                }
            } else {
                const int tok = g_rowtoken[lrow];
                if (tok >= 0) {
                    float* op = out + (size_t)tok * kD + colbase;
#pragma unroll
                    for (int nj = 0; nj < 8; nj++) {
                        const int col = wn * 64 + nj * 8 + tig * 2;
                        float2 st;
                        st.x = acc[mi][nj][rr * 2 + 0];
                        st.y = acc[mi][nj][rr * 2 + 1];
                        *(float2*)(op + col) = st;
                    }
                }
            }
        }
    }
}

// ---------------- entry ----------------
extern "C" void kernel_launch(void* const* d_in, const int* in_sizes, int n_in,
                              void* d_out, int out_size) {
    const float* hs     = (const float*)d_in[0];
    const float* logits = (const float*)d_in[1];
    const float* w1     = (const float*)d_in[2];
    const float* w2     = (const float*)d_in[3];
    float* out = (float*)d_out;

    cudaFuncSetAttribute(k_gemm<true>,  cudaFuncAttributeMaxDynamicSharedMemorySize, SMEM_BYTES);
    cudaFuncSetAttribute(k_gemm<false>, cudaFuncAttributeMaxDynamicSharedMemorySize, SMEM_BYTES);

    void* p_w1h;
    cudaGetSymbolAddress(&p_w1h, g_w1h);

    // w1 fp32->fp16 (+ zero routing counters)
    {
        long long n8 = ((long long)kE * kF * kD) / 8;
        k_cvt_w1<<<(unsigned)((n8 + 255) / 256), 256>>>((const float4*)w1, (uint4*)p_w1h, (int)n8);
    }
    // routing + permuted fp16 activations
    k_route<<<kT / 256, 256>>>(logits);
    k_offsets<<<1, 256>>>();
    k_scatter<<<kT / 256, 256>>>();
    k_permute<<<TPAD, 256>>>((const float4*)hs);

    // GEMM1 with w2-conversion CTAs folded in
    dim3 g1(kF / TN, ROWT + CVTY);
    k_gemm<true><<<g1, NTH, SMEM_BYTES>>>((const float4*)w2, nullptr);
    // GEMM2
    dim3 g2(kD / TN, ROWT);
    k_gemm<false><<<g2, NTH, SMEM_BYTES>>>(nullptr, out);
}

// round 8
// speedup vs baseline: 1.1739x; 1.0002x over previous
#include <cuda_runtime.h>
#include <cuda_fp16.h>
#include <cstdint>
#include <cstddef>

// ---------------- problem constants ----------------
namespace {
constexpr int kT = 8192, kD = 2048, kF = 4096, kE = 8;
constexpr int TMm = 128;                 // CTA tile M
constexpr int TN  = 256;                 // CTA tile N
constexpr int ROWT = kT / TMm + kE;      // 72 padded row tiles max
constexpr int TPAD = ROWT * TMm;         // 9216
constexpr int BK = 64;                   // halves per K chunk (128 B rows)
constexpr int ST = 4;                    // pipeline stages
constexpr int A_BYTES = TMm * BK * 2;    // 16 KB
constexpr int B_BYTES = TN * BK * 2;     // 32 KB
constexpr int STG = A_BYTES + B_BYTES;   // 48 KB
constexpr int SMEM_BYTES = ST * STG;     // 192 KB
constexpr int NTH = 256;                 // 8 warps
// w2 conversion folded into GEMM1 grid
constexpr int CVTY = 32;                 // 32 interleaved y-slices (x16 CTAs)
constexpr int CVT_THREADS = CVTY * 16 * NTH;         // 131072
constexpr long long W2_N8 = ((long long)kE * kD * kF) / 8;   // 8388608 uint4
}

// ---------------- scratch globals ----------------
__device__ int g_counts[kE];
__device__ int g_cursor[kE];
__device__ int g_rowtoken[TPAD];
__device__ int g_tile_expert[ROWT];
__device__ __half g_xperm[(size_t)TPAD * kD];     // permuted+padded fp16 tokens
__device__ __half g_w1h[(size_t)kE * kF * kD];
__device__ __half g_w2h[(size_t)kE * kD * kF];
__device__ __half g_h1h[(size_t)TPAD * kF];       // silu(x@w1^T) fp16

// ---------------- helpers ----------------
__device__ __forceinline__ uint32_t smem_u32(const void* p) {
    uint32_t a;
    asm("{ .reg .u64 t; cvta.to.shared.u64 t, %1; cvt.u32.u64 %0, t; }" : "=r"(a) : "l"(p));
    return a;
}
__device__ __forceinline__ void ldsm_x4(uint32_t* r, uint32_t addr) {
    asm volatile("ldmatrix.sync.aligned.m8n8.x4.shared.b16 {%0,%1,%2,%3}, [%4];"
                 : "=r"(r[0]), "=r"(r[1]), "=r"(r[2]), "=r"(r[3]) : "r"(addr));
}
__device__ __forceinline__ void mma_f16(float* c, const uint32_t* a, uint32_t b0, uint32_t b1) {
    asm volatile(
        "mma.sync.aligned.m16n8k16.row.col.f32.f16.f16.f32 "
        "{%0,%1,%2,%3}, {%4,%5,%6,%7}, {%8,%9}, {%0,%1,%2,%3};\n"
        : "+f"(c[0]), "+f"(c[1]), "+f"(c[2]), "+f"(c[3])
        : "r"(a[0]), "r"(a[1]), "r"(a[2]), "r"(a[3]), "r"(b0), "r"(b1));
}
__device__ __forceinline__ void cp_async16(uint32_t dst, const void* src) {
    asm volatile("cp.async.cg.shared.global [%0], [%1], 16;" :: "r"(dst), "l"(src));
}
__device__ __forceinline__ void cvt8(const float4* __restrict__ s, uint4* __restrict__ d) {
    float4 a = s[0], b = s[1];
    __half2 h0 = __floats2half2_rn(a.x, a.y), h1 = __floats2half2_rn(a.z, a.w);
    __half2 h2 = __floats2half2_rn(b.x, b.y), h3 = __floats2half2_rn(b.z, b.w);
    uint4 o;
    o.x = *(uint32_t*)&h0; o.y = *(uint32_t*)&h1;
    o.z = *(uint32_t*)&h2; o.w = *(uint32_t*)&h3;
    *d = o;
}

// ---------------- w1 convert (+ zero routing counters) ----------------
__global__ void k_cvt_w1(const float4* __restrict__ src, uint4* __restrict__ dst, int n8) {
    int i = blockIdx.x * blockDim.x + threadIdx.x;
    if (i < kE) g_counts[i] = 0;
    if (i >= n8) return;
    cvt8(src + 2 * (size_t)i, dst + i);
}

// ---------------- routing ----------------
__global__ void k_route(const float* __restrict__ logits) {
    int t = blockIdx.x * blockDim.x + threadIdx.x;
    if (t >= kT) return;
    const float* l = logits + (size_t)t * kE;
    int best = 0; float bv = l[0];
#pragma unroll
    for (int e = 1; e < kE; e++) { float v = l[e]; if (v > bv) { bv = v; best = e; } }
    atomicAdd(&g_counts[best], 1);
    ((int*)g_xperm)[t] = best;     // temp storage, overwritten by k_permute later
}
__global__ void k_offsets() {        // single block, 256 threads
    if (threadIdx.x == 0) {
        int off = 0;
        for (int e = 0; e < kE; e++) {
            g_cursor[e] = off;
            int nt = (g_counts[e] + TMm - 1) / TMm;
            for (int i = 0; i < nt; i++) g_tile_expert[off / TMm + i] = e;
            off += nt * TMm;
        }
        for (int rt = off / TMm; rt < ROWT; rt++) g_tile_expert[rt] = -1;
    }
    for (int i = threadIdx.x; i < TPAD; i += blockDim.x) g_rowtoken[i] = -1;
}
__global__ void k_scatter() {
    int t = blockIdx.x * blockDim.x + threadIdx.x;
    if (t >= kT) return;
    int e = ((int*)g_xperm)[t];
    int pos = atomicAdd(&g_cursor[e], 1);
    g_rowtoken[pos] = t;
}
// gather + fp32->fp16 convert + zero-pad into [TPAD, kD]
__global__ void k_permute(const float4* __restrict__ hs) {
    int i = blockIdx.x * blockDim.x + threadIdx.x;   // one per 8 halves
    int row = i >> 8;                                // kD/8 = 256 groups/row
    int q = i & 255;
    if (row >= TPAD) return;
    int tok = g_rowtoken[row];
    uint4 o = make_uint4(0, 0, 0, 0);
    if (tok >= 0) {
        const float4* s = hs + (size_t)tok * (kD / 4) + 2 * q;
        float4 a = s[0], b = s[1];
        __half2 h0 = __floats2half2_rn(a.x, a.y), h1 = __floats2half2_rn(a.z, a.w);
        __half2 h2 = __floats2half2_rn(b.x, b.y), h3 = __floats2half2_rn(b.z, b.w);
        o.x = *(uint32_t*)&h0; o.y = *(uint32_t*)&h1;
        o.z = *(uint32_t*)&h2; o.w = *(uint32_t*)&h3;
    }
    ((uint4*)g_xperm)[(size_t)row * 256 + q] = o;
}

// ---------------- fp16 HMMA GEMM -----------------------------------------
// CTA tile 128x256, 8 warps (2 M x 4 N), warp tile 64x64.
// 4-stage cp.async pipeline, 1 barrier/chunk, register-double-buffered LDSM.
// FIRST:  h1[TPAD,kF] = silu(g_xperm @ w1[e]^T); w2 fp16 conversion CTAs folded in.
// !FIRST: out[tok,kD] = g_h1h @ w2[e]^T   (scatter; pad rows dropped)
template <bool FIRST>
__global__ __launch_bounds__(NTH, 1) void k_gemm(const float4* __restrict__ w2src,
                                                 float* __restrict__ out)
{
    constexpr int N = FIRST ? kF : kD;
    constexpr int K = FIRST ? kD : kF;
    constexpr int NC = K / BK;

    int rt;
    if (FIRST) {
        // interleaved role mapping: y == 2 (mod 3) for y<96 -> w2 cvt slice
        const int y = blockIdx.y;
        if (y < 3 * CVTY && (y % 3) == 2) {
            const int slice = y / 3;
            long long base = ((long long)(slice * 16 + blockIdx.x) * NTH + threadIdx.x);
            uint4* dst = (uint4*)g_w2h;
#pragma unroll 4
            for (long long i = base; i < W2_N8; i += CVT_THREADS)
                cvt8(w2src + 2 * (size_t)i, dst + i);
            return;
        }
        rt = (y < 3 * CVTY) ? (y - (y + 1) / 3) : (y - CVTY);
    } else {
        rt = blockIdx.y;
    }

    const int e = g_tile_expert[rt];
    if (e < 0) return;
    const int rowbase = rt * TMm;
    const int colbase = blockIdx.x * TN;

    extern __shared__ char smem[];
    const uint32_t sb = smem_u32(smem);
    const int tid = threadIdx.x;
    const int warp = tid >> 5, lane = tid & 31;
    const int wm = warp & 1, wn = warp >> 1;

    const __half* Abase = FIRST ? g_xperm : g_h1h;
    const __half* Wb = (FIRST ? g_w1h : g_w2h) + (size_t)e * ((size_t)N * K);

    // ---- cp.async mapping: q = 16B group along K, r = base row ----
    const int q = tid & 7, r = tid >> 3;                 // r: 0..31
    const __half* aptr = Abase + (size_t)(rowbase + r) * K + q * 8;
    const __half* bptr = Wb + (size_t)(colbase + r) * K + q * 8;
    const uint32_t dA = (uint32_t)(r * 128 + ((q ^ (r & 7)) << 4));  // p*32 preserves row&7

    auto prefetch = [&](int c) {
        const uint32_t base = sb + (uint32_t)((c & (ST - 1)) * STG);
        const __half* ap = aptr + c * BK;
#pragma unroll
        for (int p = 0; p < 4; p++)
            cp_async16(base + dA + (uint32_t)(p * 32 * 128), ap + (size_t)p * 32 * K);
        const __half* bp = bptr + c * BK;
#pragma unroll
        for (int p = 0; p < 8; p++)
            cp_async16(base + A_BYTES + dA + (uint32_t)(p * 32 * 128), bp + (size_t)p * 32 * K);
        asm volatile("cp.async.commit_group;" ::: "memory");
    };

    prefetch(0);
    prefetch(1);
    prefetch(2);

    // ---- ldmatrix lane geometry ----
    const int rowA = wm * 64 + (lane & 15);
    const int kgA = lane >> 4;
    const int rowB = wn * 64 + ((lane >> 4) << 3) + (lane & 7);
    const int kgB = (lane >> 3) & 1;

    float acc[4][8][4];
#pragma unroll
    for (int i = 0; i < 4; i++)
#pragma unroll
        for (int j = 0; j < 8; j++)
#pragma unroll
            for (int v = 0; v < 4; v++) acc[i][j][v] = 0.f;

    // register double buffers for fragments
    uint32_t afr[2][4][4], bfr[2][4][4];

    auto load_frags = [&](uint32_t stA, uint32_t stB, int s, int buf) {
#pragma unroll
        for (int mi = 0; mi < 4; mi++) {
            const int rr = rowA + mi * 16;
            ldsm_x4(afr[buf][mi], stA + (uint32_t)(rr * 128 + (((2 * s + kgA) ^ (rr & 7)) << 4)));
        }
#pragma unroll
        for (int nj2 = 0; nj2 < 4; nj2++) {
            const int rr = rowB + nj2 * 16;
            ldsm_x4(bfr[buf][nj2], stB + (uint32_t)(rr * 128 + (((2 * s + kgB) ^ (rr & 7)) << 4)));
        }
    };

    for (int c = 0; c < NC; c++) {
        // tail-correct waits: group c must be complete before reading its stage
        if (c < NC - 2)       asm volatile("cp.async.wait_group 2;" ::: "memory");
        else if (c == NC - 2) asm volatile("cp.async.wait_group 1;" ::: "memory");
        else                  asm volatile("cp.async.wait_group 0;" ::: "memory");
        __syncthreads();                        // single barrier per chunk

        const uint32_t stA = sb + (uint32_t)((c & (ST - 1)) * STG);
        const uint32_t stB = stA + A_BYTES;

        load_frags(stA, stB, 0, 0);             // get LDSM going first
        if (c + 3 < NC) prefetch(c + 3);        // then issue next chunk's cp.async

#pragma unroll
        for (int s = 0; s < 4; s++) {           // 4 k16-steps, frag double-buffered
            if (s < 3) load_frags(stA, stB, s + 1, (s + 1) & 1);
            const int bsel = s & 1;
#pragma unroll
            for (int mi = 0; mi < 4; mi++)
#pragma unroll
                for (int nj = 0; nj < 8; nj++)
                    mma_f16(acc[mi][nj], afr[bsel][mi],
                            bfr[bsel][nj >> 1][(nj & 1) * 2],
                            bfr[bsel][nj >> 1][(nj & 1) * 2 + 1]);
        }
    }

    // ---- epilogue ----
    const int g = lane >> 2, tig = lane & 3;
#pragma unroll
    for (int mi = 0; mi < 4; mi++) {
#pragma unroll
        for (int rr = 0; rr < 2; rr++) {
            const int lrow = rowbase + wm * 64 + mi * 16 + g + rr * 8;
            if (FIRST) {
                __half* hp = g_h1h + (size_t)lrow * kF + colbase;
#pragma unroll
                for (int nj = 0; nj < 8; nj++) {
                    const int col = wn * 64 + nj * 8 + tig * 2;
                    float v0 = acc[mi][nj][rr * 2 + 0];
                    float v1 = acc[mi][nj][rr * 2 + 1];
                    v0 = v0 / (1.f + __expf(-v0));       // SiLU
                    v1 = v1 / (1.f + __expf(-v1));
                    __half2 h = __floats2half2_rn(v0, v1);
                    *(uint32_t*)(hp + col) = *(uint32_t*)&h;
                }
            } else {
                const int tok = g_rowtoken[lrow];
                if (tok >= 0) {
                    float* op = out + (size_t)tok * kD + colbase;
#pragma unroll
                    for (int nj = 0; nj < 8; nj++) {
                        const int col = wn * 64 + nj * 8 + tig * 2;
                        float2 st;
                        st.x = acc[mi][nj][rr * 2 + 0];
                        st.y = acc[mi][nj][rr * 2 + 1];
                        *(float2*)(op + col) = st;
                    }
                }
            }
        }
    }
}

// ---------------- entry ----------------
extern "C" void kernel_launch(void* const* d_in, const int* in_sizes, int n_in,
                              void* d_out, int out_size) {
    const float* hs     = (const float*)d_in[0];
    const float* logits = (const float*)d_in[1];
    const float* w1     = (const float*)d_in[2];
    const float* w2     = (const float*)d_in[3];
    float* out = (float*)d_out;

    cudaFuncSetAttribute(k_gemm<true>,  cudaFuncAttributeMaxDynamicSharedMemorySize, SMEM_BYTES);
    cudaFuncSetAttribute(k_gemm<false>, cudaFuncAttributeMaxDynamicSharedMemorySize, SMEM_BYTES);

    void* p_w1h;
    cudaGetSymbolAddress(&p_w1h, g_w1h);

    // w1 fp32->fp16 (+ zero routing counters)
    {
        long long n8 = ((long long)kE * kF * kD) / 8;
        k_cvt_w1<<<(unsigned)((n8 + 255) / 256), 256>>>((const float4*)w1, (uint4*)p_w1h, (int)n8);
    }
    // routing + permuted fp16 activations
    k_route<<<kT / 256, 256>>>(logits);
    k_offsets<<<1, 256>>>();
    k_scatter<<<kT / 256, 256>>>();
    k_permute<<<TPAD, 256>>>((const float4*)hs);

    // GEMM1 with w2-conversion CTAs folded in
    dim3 g1(kF / TN, ROWT + CVTY);
    k_gemm<true><<<g1, NTH, SMEM_BYTES>>>((const float4*)w2, nullptr);
    // GEMM2
    dim3 g2(kD / TN, ROWT);
    k_gemm<false><<<g2, NTH, SMEM_BYTES>>>(nullptr, out);
}

// round 9
// speedup vs baseline: 1.1739x; 1.0000x over previous
#include <cuda_runtime.h>
#include <cuda_fp16.h>
#include <cstdint>
#include <cstddef>

// ---------------- problem constants ----------------
namespace {
constexpr int kT = 8192, kD = 2048, kF = 4096, kE = 8;
constexpr int TMm = 128;                 // CTA tile M
constexpr int TN  = 256;                 // CTA tile N
constexpr int ROWT = kT / TMm + kE;      // 72 padded row tiles max
constexpr int TPAD = ROWT * TMm;         // 9216
constexpr int BK = 64;                   // halves per K chunk (128 B rows)
constexpr int ST = 4;                    // pipeline stages
constexpr int A_BYTES = TMm * BK * 2;    // 16 KB
constexpr int B_BYTES = TN * BK * 2;     // 32 KB
constexpr int STG = A_BYTES + B_BYTES;   // 48 KB
constexpr int SMEM_BYTES = ST * STG;     // 192 KB
constexpr int NTH = 256;                 // 8 warps
// w2 conversion folded into GEMM1 grid
constexpr int CVTY = 32;                 // 32 interleaved y-slices (x16 CTAs)
constexpr int CVT_THREADS = CVTY * 16 * NTH;         // 131072
constexpr long long W2_N8 = ((long long)kE * kD * kF) / 8;   // 8388608 uint4
}

// ---------------- scratch globals ----------------
__device__ int g_counts[kE];
__device__ int g_cursor[kE];
__device__ int g_rowtoken[TPAD];
__device__ int g_tile_expert[ROWT];
__device__ __half g_xperm[(size_t)TPAD * kD];     // permuted+padded fp16 tokens
__device__ __half g_w1h[(size_t)kE * kF * kD];
__device__ __half g_w2h[(size_t)kE * kD * kF];
__device__ __half g_h1h[(size_t)TPAD * kF];       // silu(x@w1^T) fp16

// ---------------- helpers ----------------
__device__ __forceinline__ uint32_t smem_u32(const void* p) {
    uint32_t a;
    asm("{ .reg .u64 t; cvta.to.shared.u64 t, %1; cvt.u32.u64 %0, t; }" : "=r"(a) : "l"(p));
    return a;
}
__device__ __forceinline__ void ldsm_x4(uint32_t* r, uint32_t addr) {
    asm volatile("ldmatrix.sync.aligned.m8n8.x4.shared.b16 {%0,%1,%2,%3}, [%4];"
                 : "=r"(r[0]), "=r"(r[1]), "=r"(r[2]), "=r"(r[3]) : "r"(addr));
}
__device__ __forceinline__ void mma_f16(float* c, const uint32_t* a, uint32_t b0, uint32_t b1) {
    asm volatile(
        "mma.sync.aligned.m16n8k16.row.col.f32.f16.f16.f32 "
        "{%0,%1,%2,%3}, {%4,%5,%6,%7}, {%8,%9}, {%0,%1,%2,%3};\n"
        : "+f"(c[0]), "+f"(c[1]), "+f"(c[2]), "+f"(c[3])
        : "r"(a[0]), "r"(a[1]), "r"(a[2]), "r"(a[3]), "r"(b0), "r"(b1));
}
__device__ __forceinline__ void cp_async16(uint32_t dst, const void* src) {
    asm volatile("cp.async.cg.shared.global [%0], [%1], 16;" :: "r"(dst), "l"(src));
}
__device__ __forceinline__ void cvt8(const float4* __restrict__ s, uint4* __restrict__ d) {
    float4 a = s[0], b = s[1];
    __half2 h0 = __floats2half2_rn(a.x, a.y), h1 = __floats2half2_rn(a.z, a.w);
    __half2 h2 = __floats2half2_rn(b.x, b.y), h3 = __floats2half2_rn(b.z, b.w);
    uint4 o;
    o.x = *(uint32_t*)&h0; o.y = *(uint32_t*)&h1;
    o.z = *(uint32_t*)&h2; o.w = *(uint32_t*)&h3;
    *d = o;
}

// ---------------- w1 convert (+ zero routing counters) ----------------
__global__ void k_cvt_w1(const float4* __restrict__ src, uint4* __restrict__ dst, int n8) {
    int i = blockIdx.x * blockDim.x + threadIdx.x;
    if (i < kE) g_counts[i] = 0;
    if (i >= n8) return;
    cvt8(src + 2 * (size_t)i, dst + i);
}

// ---------------- routing ----------------
__global__ void k_route(const float* __restrict__ logits) {
    int t = blockIdx.x * blockDim.x + threadIdx.x;
    if (t >= kT) return;
    const float* l = logits + (size_t)t * kE;
    int best = 0; float bv = l[0];
#pragma unroll
    for (int e = 1; e < kE; e++) { float v = l[e]; if (v > bv) { bv = v; best = e; } }
    atomicAdd(&g_counts[best], 1);
    ((int*)g_xperm)[t] = best;     // temp storage, overwritten by k_permute later
}
__global__ void k_offsets() {        // single block, 256 threads
    if (threadIdx.x == 0) {
        int off = 0;
        for (int e = 0; e < kE; e++) {
            g_cursor[e] = off;
            int nt = (g_counts[e] + TMm - 1) / TMm;
            for (int i = 0; i < nt; i++) g_tile_expert[off / TMm + i] = e;
            off += nt * TMm;
        }
        for (int rt = off / TMm; rt < ROWT; rt++) g_tile_expert[rt] = -1;
    }
    for (int i = threadIdx.x; i < TPAD; i += blockDim.x) g_rowtoken[i] = -1;
}
__global__ void k_scatter() {
    int t = blockIdx.x * blockDim.x + threadIdx.x;
    if (t >= kT) return;
    int e = ((int*)g_xperm)[t];
    int pos = atomicAdd(&g_cursor[e], 1);
    g_rowtoken[pos] = t;
}
// gather + fp32->fp16 convert + zero-pad into [TPAD, kD]
__global__ void k_permute(const float4* __restrict__ hs) {
    int i = blockIdx.x * blockDim.x + threadIdx.x;   // one per 8 halves
    int row = i >> 8;                                // kD/8 = 256 groups/row
    int q = i & 255;
    if (row >= TPAD) return;
    int tok = g_rowtoken[row];
    uint4 o = make_uint4(0, 0, 0, 0);
    if (tok >= 0) {
        const float4* s = hs + (size_t)tok * (kD / 4) + 2 * q;
        float4 a = s[0], b = s[1];
        __half2 h0 = __floats2half2_rn(a.x, a.y), h1 = __floats2half2_rn(a.z, a.w);
        __half2 h2 = __floats2half2_rn(b.x, b.y), h3 = __floats2half2_rn(b.z, b.w);
        o.x = *(uint32_t*)&h0; o.y = *(uint32_t*)&h1;
        o.z = *(uint32_t*)&h2; o.w = *(uint32_t*)&h3;
    }
    ((uint4*)g_xperm)[(size_t)row * 256 + q] = o;
}

// ---------------- fp16 HMMA GEMM -----------------------------------------
// CTA tile 128x256, 8 warps (2 M x 4 N), warp tile 64x64.
// 4-stage cp.async pipeline, 1 barrier/chunk, register-double-buffered LDSM.
// FIRST:  h1[TPAD,kF] = silu(g_xperm @ w1[e]^T); w2 fp16 conversion CTAs folded in.
// !FIRST: out[tok,kD] = g_h1h @ w2[e]^T   (scatter; pad rows dropped)
template <bool FIRST>
__global__ __launch_bounds__(NTH, 1) void k_gemm(const float4* __restrict__ w2src,
                                                 float* __restrict__ out)
{
    constexpr int N = FIRST ? kF : kD;
    constexpr int K = FIRST ? kD : kF;
    constexpr int NC = K / BK;

    int rt;
    if (FIRST) {
        // interleaved role mapping: y == 2 (mod 3) for y<96 -> w2 cvt slice
        const int y = blockIdx.y;
        if (y < 3 * CVTY && (y % 3) == 2) {
            const int slice = y / 3;
            long long base = ((long long)(slice * 16 + blockIdx.x) * NTH + threadIdx.x);
            uint4* dst = (uint4*)g_w2h;
#pragma unroll 4
            for (long long i = base; i < W2_N8; i += CVT_THREADS)
                cvt8(w2src + 2 * (size_t)i, dst + i);
            return;
        }
        rt = (y < 3 * CVTY) ? (y - (y + 1) / 3) : (y - CVTY);
    } else {
        rt = blockIdx.y;
    }

    const int e = g_tile_expert[rt];
    if (e < 0) return;
    const int rowbase = rt * TMm;
    const int colbase = blockIdx.x * TN;

    extern __shared__ char smem[];
    const uint32_t sb = smem_u32(smem);
    const int tid = threadIdx.x;
    const int warp = tid >> 5, lane = tid & 31;
    const int wm = warp & 1, wn = warp >> 1;

    const __half* Abase = FIRST ? g_xperm : g_h1h;
    const __half* Wb = (FIRST ? g_w1h : g_w2h) + (size_t)e * ((size_t)N * K);

    // ---- cp.async mapping: q = 16B group along K, r = base row ----
    const int q = tid & 7, r = tid >> 3;                 // r: 0..31
    const __half* aptr = Abase + (size_t)(rowbase + r) * K + q * 8;
    const __half* bptr = Wb + (size_t)(colbase + r) * K + q * 8;
    const uint32_t dA = (uint32_t)(r * 128 + ((q ^ (r & 7)) << 4));  // p*32 preserves row&7

    auto prefetch = [&](int c) {
        const uint32_t base = sb + (uint32_t)((c & (ST - 1)) * STG);
        const __half* ap = aptr + c * BK;
#pragma unroll
        for (int p = 0; p < 4; p++)
            cp_async16(base + dA + (uint32_t)(p * 32 * 128), ap + (size_t)p * 32 * K);
        const __half* bp = bptr + c * BK;
#pragma unroll
        for (int p = 0; p < 8; p++)
            cp_async16(base + A_BYTES + dA + (uint32_t)(p * 32 * 128), bp + (size_t)p * 32 * K);
        asm volatile("cp.async.commit_group;" ::: "memory");
    };

    prefetch(0);
    prefetch(1);
    prefetch(2);

    // ---- ldmatrix lane geometry ----
    const int rowA = wm * 64 + (lane & 15);
    const int kgA = lane >> 4;
    const int rowB = wn * 64 + ((lane >> 4) << 3) + (lane & 7);
    const int kgB = (lane >> 3) & 1;

    float acc[4][8][4];
#pragma unroll
    for (int i = 0; i < 4; i++)
#pragma unroll
        for (int j = 0; j < 8; j++)
#pragma unroll
            for (int v = 0; v < 4; v++) acc[i][j][v] = 0.f;

    // register double buffers for fragments
    uint32_t afr[2][4][4], bfr[2][4][4];

    auto load_frags = [&](uint32_t stA, uint32_t stB, int s, int buf) {
#pragma unroll
        for (int mi = 0; mi < 4; mi++) {
            const int rr = rowA + mi * 16;
            ldsm_x4(afr[buf][mi], stA + (uint32_t)(rr * 128 + (((2 * s + kgA) ^ (rr & 7)) << 4)));
        }
#pragma unroll
        for (int nj2 = 0; nj2 < 4; nj2++) {
            const int rr = rowB + nj2 * 16;
            ldsm_x4(bfr[buf][nj2], stB + (uint32_t)(rr * 128 + (((2 * s + kgB) ^ (rr & 7)) << 4)));
        }
    };

    for (int c = 0; c < NC; c++) {
        // tail-correct waits: group c must be complete before reading its stage
        if (c < NC - 2)       asm volatile("cp.async.wait_group 2;" ::: "memory");
        else if (c == NC - 2) asm volatile("cp.async.wait_group 1;" ::: "memory");
        else                  asm volatile("cp.async.wait_group 0;" ::: "memory");
        __syncthreads();                        // single barrier per chunk

        const uint32_t stA = sb + (uint32_t)((c & (ST - 1)) * STG);
        const uint32_t stB = stA + A_BYTES;

        load_frags(stA, stB, 0, 0);             // get LDSM going first
        if (c + 3 < NC) prefetch(c + 3);        // then issue next chunk's cp.async

#pragma unroll
        for (int s = 0; s < 4; s++) {           // 4 k16-steps, frag double-buffered
            if (s < 3) load_frags(stA, stB, s + 1, (s + 1) & 1);
            const int bsel = s & 1;
#pragma unroll
            for (int mi = 0; mi < 4; mi++)
#pragma unroll
                for (int nj = 0; nj < 8; nj++)
                    mma_f16(acc[mi][nj], afr[bsel][mi],
                            bfr[bsel][nj >> 1][(nj & 1) * 2],
                            bfr[bsel][nj >> 1][(nj & 1) * 2 + 1]);
        }
    }

    // ---- epilogue ----
    const int g = lane >> 2, tig = lane & 3;
#pragma unroll
    for (int mi = 0; mi < 4; mi++) {
#pragma unroll
        for (int rr = 0; rr < 2; rr++) {
            const int lrow = rowbase + wm * 64 + mi * 16 + g + rr * 8;
            if (FIRST) {
                __half* hp = g_h1h + (size_t)lrow * kF + colbase;
#pragma unroll
                for (int nj = 0; nj < 8; nj++) {
                    const int col = wn * 64 + nj * 8 + tig * 2;
                    float v0 = acc[mi][nj][rr * 2 + 0];
                    float v1 = acc[mi][nj][rr * 2 + 1];
                    v0 = v0 / (1.f + __expf(-v0));       // SiLU
                    v1 = v1 / (1.f + __expf(-v1));
                    __half2 h = __floats2half2_rn(v0, v1);
                    *(uint32_t*)(hp + col) = *(uint32_t*)&h;
                }
            } else {
                const int tok = g_rowtoken[lrow];
                if (tok >= 0) {
                    float* op = out + (size_t)tok * kD + colbase;
#pragma unroll
                    for (int nj = 0; nj < 8; nj++) {
                        const int col = wn * 64 + nj * 8 + tig * 2;
                        float2 st;
                        st.x = acc[mi][nj][rr * 2 + 0];
                        st.y = acc[mi][nj][rr * 2 + 1];
                        *(float2*)(op + col) = st;
                    }
                }
            }
        }
    }
}

// ---------------- entry ----------------
extern "C" void kernel_launch(void* const* d_in, const int* in_sizes, int n_in,
                              void* d_out, int out_size) {
    const float* hs     = (const float*)d_in[0];
    const float* logits = (const float*)d_in[1];
    const float* w1     = (const float*)d_in[2];
    const float* w2     = (const float*)d_in[3];
    float* out = (float*)d_out;

    cudaFuncSetAttribute(k_gemm<true>,  cudaFuncAttributeMaxDynamicSharedMemorySize, SMEM_BYTES);
    cudaFuncSetAttribute(k_gemm<false>, cudaFuncAttributeMaxDynamicSharedMemorySize, SMEM_BYTES);

    void* p_w1h;
    cudaGetSymbolAddress(&p_w1h, g_w1h);

    // w1 fp32->fp16 (+ zero routing counters)
    {
        long long n8 = ((long long)kE * kF * kD) / 8;
        k_cvt_w1<<<(unsigned)((n8 + 255) / 256), 256>>>((const float4*)w1, (uint4*)p_w1h, (int)n8);
    }
    // routing + permuted fp16 activations
    k_route<<<kT / 256, 256>>>(logits);
    k_offsets<<<1, 256>>>();
    k_scatter<<<kT / 256, 256>>>();
    k_permute<<<TPAD, 256>>>((const float4*)hs);

    // GEMM1 with w2-conversion CTAs folded in
    dim3 g1(kF / TN, ROWT + CVTY);
    k_gemm<true><<<g1, NTH, SMEM_BYTES>>>((const float4*)w2, nullptr);
    // GEMM2
    dim3 g2(kD / TN, ROWT);
    k_gemm<false><<<g2, NTH, SMEM_BYTES>>>(nullptr, out);
}

// round 10
// speedup vs baseline: 1.3176x; 1.1224x over previous
#include <cuda_runtime.h>
#include <cuda_fp16.h>
#include <cstdint>
#include <cstddef>

// ---------------- problem constants ----------------
namespace {
constexpr int kT = 8192, kD = 2048, kF = 4096, kE = 8;
constexpr int TMm = 128;                 // CTA tile M
constexpr int TN  = 128;                 // CTA tile N
constexpr int ROWT = kT / TMm + kE;      // 72 padded row tiles max
constexpr int TPAD = ROWT * TMm;         // 9216
constexpr int BK = 64;                   // halves per K chunk (128 B rows)
constexpr int ST = 3;                    // pipeline stages
constexpr int A_BYTES = TMm * BK * 2;    // 16 KB
constexpr int B_BYTES = TN * BK * 2;     // 16 KB
constexpr int STG = A_BYTES + B_BYTES;   // 32 KB
constexpr int SMEM_BYTES = ST * STG;     // 96 KB  -> 2 CTAs/SM
constexpr int NTH = 128;                 // 4 warps, warp tile 64x64
// w2 conversion folded into GEMM1 grid (gridDim.x = kF/TN = 32)
constexpr int CVTY = 16;                 // 16 interleaved y-slices (x32 CTAs)
constexpr int CVT_THREADS = CVTY * 32 * NTH;          // 65536
constexpr long long W2_N8 = ((long long)kE * kD * kF) / 8;   // 8388608 uint4
}

// ---------------- scratch globals ----------------
__device__ int g_counts[kE];
__device__ int g_cursor[kE];
__device__ int g_rowtoken[TPAD];
__device__ int g_tile_expert[ROWT];
__device__ __half g_xperm[(size_t)TPAD * kD];     // permuted+padded fp16 tokens
__device__ __half g_w1h[(size_t)kE * kF * kD];
__device__ __half g_w2h[(size_t)kE * kD * kF];
__device__ __half g_h1h[(size_t)TPAD * kF];       // silu(x@w1^T) fp16

// ---------------- helpers ----------------
__device__ __forceinline__ uint32_t smem_u32(const void* p) {
    uint32_t a;
    asm("{ .reg .u64 t; cvta.to.shared.u64 t, %1; cvt.u32.u64 %0, t; }" : "=r"(a) : "l"(p));
    return a;
}
__device__ __forceinline__ void ldsm_x4(uint32_t* r, uint32_t addr) {
    asm volatile("ldmatrix.sync.aligned.m8n8.x4.shared.b16 {%0,%1,%2,%3}, [%4];"
                 : "=r"(r[0]), "=r"(r[1]), "=r"(r[2]), "=r"(r[3]) : "r"(addr));
}
__device__ __forceinline__ void mma_f16(float* c, const uint32_t* a, uint32_t b0, uint32_t b1) {
    asm volatile(
        "mma.sync.aligned.m16n8k16.row.col.f32.f16.f16.f32 "
        "{%0,%1,%2,%3}, {%4,%5,%6,%7}, {%8,%9}, {%0,%1,%2,%3};\n"
        : "+f"(c[0]), "+f"(c[1]), "+f"(c[2]), "+f"(c[3])
        : "r"(a[0]), "r"(a[1]), "r"(a[2]), "r"(a[3]), "r"(b0), "r"(b1));
}
__device__ __forceinline__ void cp_async16(uint32_t dst, const void* src) {
    asm volatile("cp.async.cg.shared.global [%0], [%1], 16;" :: "r"(dst), "l"(src));
}
__device__ __forceinline__ void cvt8(const float4* __restrict__ s, uint4* __restrict__ d) {
    float4 a = s[0], b = s[1];
    __half2 h0 = __floats2half2_rn(a.x, a.y), h1 = __floats2half2_rn(a.z, a.w);
    __half2 h2 = __floats2half2_rn(b.x, b.y), h3 = __floats2half2_rn(b.z, b.w);
    uint4 o;
    o.x = *(uint32_t*)&h0; o.y = *(uint32_t*)&h1;
    o.z = *(uint32_t*)&h2; o.w = *(uint32_t*)&h3;
    *d = o;
}

// ---------------- w1 convert (+ zero routing counters) ----------------
__global__ void k_cvt_w1(const float4* __restrict__ src, uint4* __restrict__ dst, int n8) {
    int i = blockIdx.x * blockDim.x + threadIdx.x;
    if (i < kE) g_counts[i] = 0;
    if (i >= n8) return;
    cvt8(src + 2 * (size_t)i, dst + i);
}

// ---------------- routing ----------------
__global__ void k_route(const float* __restrict__ logits) {
    int t = blockIdx.x * blockDim.x + threadIdx.x;
    if (t >= kT) return;
    const float* l = logits + (size_t)t * kE;
    int best = 0; float bv = l[0];
#pragma unroll
    for (int e = 1; e < kE; e++) { float v = l[e]; if (v > bv) { bv = v; best = e; } }
    atomicAdd(&g_counts[best], 1);
    ((int*)g_xperm)[t] = best;     // temp storage, overwritten by k_permute later
}
__global__ void k_offsets() {        // single block, 256 threads
    if (threadIdx.x == 0) {
        int off = 0;
        for (int e = 0; e < kE; e++) {
            g_cursor[e] = off;
            int nt = (g_counts[e] + TMm - 1) / TMm;
            for (int i = 0; i < nt; i++) g_tile_expert[off / TMm + i] = e;
            off += nt * TMm;
        }
        for (int rt = off / TMm; rt < ROWT; rt++) g_tile_expert[rt] = -1;
    }
    for (int i = threadIdx.x; i < TPAD; i += blockDim.x) g_rowtoken[i] = -1;
}
__global__ void k_scatter() {
    int t = blockIdx.x * blockDim.x + threadIdx.x;
    if (t >= kT) return;
    int e = ((int*)g_xperm)[t];
    int pos = atomicAdd(&g_cursor[e], 1);
    g_rowtoken[pos] = t;
}
// gather + fp32->fp16 convert + zero-pad into [TPAD, kD]
__global__ void k_permute(const float4* __restrict__ hs) {
    int i = blockIdx.x * blockDim.x + threadIdx.x;   // one per 8 halves
    int row = i >> 8;                                // kD/8 = 256 groups/row
    int q = i & 255;
    if (row >= TPAD) return;
    int tok = g_rowtoken[row];
    uint4 o = make_uint4(0, 0, 0, 0);
    if (tok >= 0) {
        const float4* s = hs + (size_t)tok * (kD / 4) + 2 * q;
        float4 a = s[0], b = s[1];
        __half2 h0 = __floats2half2_rn(a.x, a.y), h1 = __floats2half2_rn(a.z, a.w);
        __half2 h2 = __floats2half2_rn(b.x, b.y), h3 = __floats2half2_rn(b.z, b.w);
        o.x = *(uint32_t*)&h0; o.y = *(uint32_t*)&h1;
        o.z = *(uint32_t*)&h2; o.w = *(uint32_t*)&h3;
    }
    ((uint4*)g_xperm)[(size_t)row * 256 + q] = o;
}

// ---------------- fp16 HMMA GEMM -----------------------------------------
// CTA tile 128x128, 4 warps (2 M x 2 N), warp tile 64x64, occupancy 2.
// 3-stage cp.async pipeline, 1 barrier/chunk.
// FIRST:  h1[TPAD,kF] = silu(g_xperm @ w1[e]^T); w2 fp16 conversion CTAs folded in.
// !FIRST: out[tok,kD] = g_h1h @ w2[e]^T   (scatter; pad rows dropped)
template <bool FIRST>
__global__ __launch_bounds__(NTH, 2) void k_gemm(const float4* __restrict__ w2src,
                                                 float* __restrict__ out)
{
    constexpr int N = FIRST ? kF : kD;
    constexpr int K = FIRST ? kD : kF;
    constexpr int NC = K / BK;

    int rt;
    if (FIRST) {
        // interleaved role mapping: y == 2 (mod 3) for y<48 -> w2 cvt slice
        const int y = blockIdx.y;
        if (y < 3 * CVTY && (y % 3) == 2) {
            const int slice = y / 3;
            long long base = ((long long)(slice * 32 + blockIdx.x) * NTH + threadIdx.x);
            uint4* dst = (uint4*)g_w2h;
#pragma unroll 4
            for (long long i = base; i < W2_N8; i += CVT_THREADS)
                cvt8(w2src + 2 * (size_t)i, dst + i);
            return;
        }
        rt = (y < 3 * CVTY) ? (y - (y + 1) / 3) : (y - CVTY);
    } else {
        rt = blockIdx.y;
    }

    const int e = g_tile_expert[rt];
    if (e < 0) return;
    const int rowbase = rt * TMm;
    const int colbase = blockIdx.x * TN;

    extern __shared__ char smem[];
    const uint32_t sb = smem_u32(smem);
    const int tid = threadIdx.x;
    const int warp = tid >> 5, lane = tid & 31;
    const int wm = warp & 1, wn = warp >> 1;   // 2 x 2 warps, 64x64 each

    const __half* Abase = FIRST ? g_xperm : g_h1h;
    const __half* Wb = (FIRST ? g_w1h : g_w2h) + (size_t)e * ((size_t)N * K);

    // ---- cp.async mapping: q = 16B group along K, r = base row (0..15) ----
    const int q = tid & 7, r = tid >> 3;
    const __half* aptr = Abase + (size_t)(rowbase + r) * K + q * 8;
    const __half* bptr = Wb + (size_t)(colbase + r) * K + q * 8;
    const uint32_t dA = (uint32_t)(r * 128 + ((q ^ (r & 7)) << 4));  // p*16 preserves row&7

    auto prefetch = [&](int c) {
        const uint32_t base = sb + (uint32_t)((c % ST) * STG);
        const __half* ap = aptr + c * BK;
#pragma unroll
        for (int p = 0; p < 8; p++)
            cp_async16(base + dA + (uint32_t)(p * 16 * 128), ap + (size_t)p * 16 * K);
        const __half* bp = bptr + c * BK;
#pragma unroll
        for (int p = 0; p < 8; p++)
            cp_async16(base + A_BYTES + dA + (uint32_t)(p * 16 * 128), bp + (size_t)p * 16 * K);
        asm volatile("cp.async.commit_group;" ::: "memory");
    };

    prefetch(0);
    prefetch(1);

    // ---- ldmatrix lane geometry ----
    const int rowA = wm * 64 + (lane & 15);
    const int kgA = lane >> 4;
    const int rowB = wn * 64 + ((lane >> 4) << 3) + (lane & 7);
    const int kgB = (lane >> 3) & 1;

    float acc[4][8][4];
#pragma unroll
    for (int i = 0; i < 4; i++)
#pragma unroll
        for (int j = 0; j < 8; j++)
#pragma unroll
            for (int v = 0; v < 4; v++) acc[i][j][v] = 0.f;

    for (int c = 0; c < NC; c++) {
        // tail-correct wait: group c must be complete before reading its stage
        if (c < NC - 1) asm volatile("cp.async.wait_group 1;" ::: "memory");
        else            asm volatile("cp.async.wait_group 0;" ::: "memory");
        __syncthreads();                        // single barrier per chunk (4 warps)
        if (c + 2 < NC) prefetch(c + 2);

        const uint32_t stA = sb + (uint32_t)((c % ST) * STG);
        const uint32_t stB = stA + A_BYTES;
#pragma unroll
        for (int s = 0; s < 4; s++) {           // 4 k16-steps
            uint32_t a[4][4];
#pragma unroll
            for (int mi = 0; mi < 4; mi++) {
                const int rr = rowA + mi * 16;
                ldsm_x4(a[mi], stA + (uint32_t)(rr * 128 + (((2 * s + kgA) ^ (rr & 7)) << 4)));
            }
            uint32_t b[4][4];
#pragma unroll
            for (int nj2 = 0; nj2 < 4; nj2++) {
                const int rr = rowB + nj2 * 16;
                ldsm_x4(b[nj2], stB + (uint32_t)(rr * 128 + (((2 * s + kgB) ^ (rr & 7)) << 4)));
            }
#pragma unroll
            for (int mi = 0; mi < 4; mi++)
#pragma unroll
                for (int nj = 0; nj < 8; nj++)
                    mma_f16(acc[mi][nj], a[mi], b[nj >> 1][(nj & 1) * 2], b[nj >> 1][(nj & 1) * 2 + 1]);
        }
    }

    // ---- epilogue ----
    const int g = lane >> 2, tig = lane & 3;
#pragma unroll
    for (int mi = 0; mi < 4; mi++) {
#pragma unroll
        for (int rr = 0; rr < 2; rr++) {
            const int lrow = rowbase + wm * 64 + mi * 16 + g + rr * 8;
            if (FIRST) {
                __half* hp = g_h1h + (size_t)lrow * kF + colbase;
#pragma unroll
                for (int nj = 0; nj < 8; nj++) {
                    const int col = wn * 64 + nj * 8 + tig * 2;
                    float v0 = acc[mi][nj][rr * 2 + 0];
                    float v1 = acc[mi][nj][rr * 2 + 1];
                    v0 = v0 / (1.f + __expf(-v0));       // SiLU
                    v1 = v1 / (1.f + __expf(-v1));
                    __half2 h = __floats2half2_rn(v0, v1);
                    *(uint32_t*)(hp + col) = *(uint32_t*)&h;
                }
            } else {
                const int tok = g_rowtoken[lrow];
                if (tok >= 0) {
                    float* op = out + (size_t)tok * kD + colbase;
#pragma unroll
                    for (int nj = 0; nj < 8; nj++) {
                        const int col = wn * 64 + nj * 8 + tig * 2;
                        float2 st;
                        st.x = acc[mi][nj][rr * 2 + 0];
                        st.y = acc[mi][nj][rr * 2 + 1];
                        *(float2*)(op + col) = st;
                    }
                }
            }
        }
    }
}

// ---------------- entry ----------------
extern "C" void kernel_launch(void* const* d_in, const int* in_sizes, int n_in,
                              void* d_out, int out_size) {
    const float* hs     = (const float*)d_in[0];
    const float* logits = (const float*)d_in[1];
    const float* w1     = (const float*)d_in[2];
    const float* w2     = (const float*)d_in[3];
    float* out = (float*)d_out;

    cudaFuncSetAttribute(k_gemm<true>,  cudaFuncAttributeMaxDynamicSharedMemorySize, SMEM_BYTES);
    cudaFuncSetAttribute(k_gemm<false>, cudaFuncAttributeMaxDynamicSharedMemorySize, SMEM_BYTES);

    void* p_w1h;
    cudaGetSymbolAddress(&p_w1h, g_w1h);

    // w1 fp32->fp16 (+ zero routing counters)
    {
        long long n8 = ((long long)kE * kF * kD) / 8;
        k_cvt_w1<<<(unsigned)((n8 + 255) / 256), 256>>>((const float4*)w1, (uint4*)p_w1h, (int)n8);
    }
    // routing + permuted fp16 activations
    k_route<<<kT / 256, 256>>>(logits);
    k_offsets<<<1, 256>>>();
    k_scatter<<<kT / 256, 256>>>();
    k_permute<<<TPAD, 256>>>((const float4*)hs);

    // GEMM1 with w2-conversion CTAs folded in
    dim3 g1(kF / TN, ROWT + CVTY);
    k_gemm<true><<<g1, NTH, SMEM_BYTES>>>((const float4*)w2, nullptr);
    // GEMM2
    dim3 g2(kD / TN, ROWT);
    k_gemm<false><<<g2, NTH, SMEM_BYTES>>>(nullptr, out);
}